// round 9
// baseline (speedup 1.0000x reference)
#include <cuda_runtime.h>
#include <cstdint>
#include <cstddef>

// Problem constants (AttentionPool: B=8, T=4096, D=1024, G=64)
#define B_  8
#define T_  4096
#define D_  1024
#define G_  64
#define BT_ (B_ * T_)           // 32768 tokens
#define BG_ (B_ * G_)           // 512 (b,g) pairs
#define EPS_ 1.1920928955078125e-07f   // finfo(float32).eps
#define INV_SQRT_D_ (1.0f / 32.0f)

typedef unsigned long long u64;

// ---------------------------------------------------------------------------
// Device scratch (static — no allocations allowed)
// ---------------------------------------------------------------------------
__device__ float  g_qkd[D_];                // norm_w * (Wk^T q)
__device__ float  g_score[BT_];             // per-token score
__device__ float  g_invrms[BT_];            // per-token 1/rms
__device__ float2 g_wg[BT_];                // {coef, group_as_bits} per token
__device__ float  g_p4[4][BG_ * D_];        // pooled h partials (token split 4)
__device__ float  g_out_part[4][BG_ * D_];  // split-K GEMM partials

// ---------------------------------------------------------------------------
// helpers
// ---------------------------------------------------------------------------
__device__ __forceinline__ u64 pack2(float v) {
    u64 r; asm("mov.b64 %0, {%1, %1};" : "=l"(r) : "f"(v)); return r;
}
__device__ __forceinline__ u64 fma2(u64 a, u64 b, u64 c) {
    u64 d; asm("fma.rn.f32x2 %0, %1, %2, %3;" : "=l"(d) : "l"(a), "l"(b), "l"(c));
    return d;
}
__device__ __forceinline__ void cp16(uint32_t smem_dst, const void* gsrc) {
    asm volatile("cp.async.cg.shared.global [%0], [%1], 16;"
                 :: "r"(smem_dst), "l"(gsrc));
}
__device__ __forceinline__ void cp_commit() {
    asm volatile("cp.async.commit_group;");
}
template <int N>
__device__ __forceinline__ void cp_wait() {
    asm volatile("cp.async.wait_group %0;" :: "n"(N));
}
// volatile loads: CANNOT be sunk or reordered by ptxas -> true front-batching
__device__ __forceinline__ float vldg(const float* p) {
    float r; asm volatile("ld.global.nc.f32 %0, [%1];" : "=f"(r) : "l"(p));
    return r;
}
__device__ __forceinline__ float4 vldg4(const float* p) {
    float4 r;
    asm volatile("ld.global.nc.v4.f32 {%0,%1,%2,%3}, [%4];"
                 : "=f"(r.x), "=f"(r.y), "=f"(r.z), "=f"(r.w) : "l"(p));
    return r;
}

// ---------------------------------------------------------------------------
// Kernel 0: fused qk GEMV  qkd[d] = norm_w[d] * sum_e query[e] * Wk[e,d]
// ---------------------------------------------------------------------------
__global__ void __launch_bounds__(256) qk_kernel(
    const float* __restrict__ query, const float* __restrict__ Wk,
    const float* __restrict__ norm_w) {
    int di = threadIdx.x & 15;
    int eg = threadIdx.x >> 4;
    int d  = blockIdx.x * 16 + di;
    float s = 0.f;
    #pragma unroll 8
    for (int e = eg; e < D_; e += 16) s += query[e] * Wk[(size_t)e * D_ + d];
    __shared__ float red[16][17];
    red[eg][di] = s;
    __syncthreads();
    if (threadIdx.x < 16) {
        int dd = blockIdx.x * 16 + threadIdx.x;
        float t = 0.f;
        #pragma unroll
        for (int i = 0; i < 16; i++) t += red[i][threadIdx.x];
        g_qkd[dd] = t * norm_w[dd];
    }
}

// ---------------------------------------------------------------------------
// Kernel 1: per-token stats v3 — 2 tokens/warp, 16 volatile LDG.128
// front-batched by construction (4KB in flight per warp).
// ---------------------------------------------------------------------------
__global__ void __launch_bounds__(256) token_stats_kernel(const float* __restrict__ x) {
    int w    = threadIdx.x >> 5;
    int lane = threadIdx.x & 31;
    int tok0 = blockIdx.x * 16 + w * 2;
    int tok1 = tok0 + 1;
    const float* xt0 = x + (size_t)tok0 * D_;
    const float* xt1 = x + (size_t)tok1 * D_;
    const float4* qk = (const float4*)g_qkd;

    float4 a[8], c[8];
    #pragma unroll
    for (int r = 0; r < 8; r++) a[r] = vldg4(xt0 + (r * 32 + lane) * 4);
    #pragma unroll
    for (int r = 0; r < 8; r++) c[r] = vldg4(xt1 + (r * 32 + lane) * 4);

    float ss0 = 0.f, dq0 = 0.f, ss1 = 0.f, dq1 = 0.f;
    #pragma unroll
    for (int r = 0; r < 8; r++) {
        float4 q = qk[r * 32 + lane];    // L1-resident (4KB, shared by all)
        float4 v = a[r];
        ss0 += v.x * v.x + v.y * v.y + v.z * v.z + v.w * v.w;
        dq0 += v.x * q.x + v.y * q.y + v.z * q.z + v.w * q.w;
        float4 u = c[r];
        ss1 += u.x * u.x + u.y * u.y + u.z * u.z + u.w * u.w;
        dq1 += u.x * q.x + u.y * q.y + u.z * q.z + u.w * q.w;
    }
    #pragma unroll
    for (int o = 16; o; o >>= 1) {
        ss0 += __shfl_xor_sync(0xffffffffu, ss0, o);
        dq0 += __shfl_xor_sync(0xffffffffu, dq0, o);
        ss1 += __shfl_xor_sync(0xffffffffu, ss1, o);
        dq1 += __shfl_xor_sync(0xffffffffu, dq1, o);
    }
    if (lane == 0) {
        float ir0 = rsqrtf(ss0 * (1.0f / (float)D_) + EPS_);
        g_invrms[tok0] = ir0;
        g_score[tok0]  = dq0 * ir0 * INV_SQRT_D_;
        float ir1 = rsqrtf(ss1 * (1.0f / (float)D_) + EPS_);
        g_invrms[tok1] = ir1;
        g_score[tok1]  = dq1 * ir1 * INV_SQRT_D_;
    }
}

// ---------------------------------------------------------------------------
// Kernel 2: segment softmax per (b,g) + per-token coef write.
// ---------------------------------------------------------------------------
__global__ void __launch_bounds__(128) seg_softmax_kernel(const unsigned int* __restrict__ raw) {
    int b = blockIdx.x >> 6;
    int g = blockIdx.x & 63;
    int tid = threadIdx.x;

    unsigned int det = raw[2 * tid + 1];
    #pragma unroll
    for (int o = 16; o; o >>= 1) det |= __shfl_xor_sync(0xffffffffu, det, o);
    __shared__ unsigned int sdet[4];
    if ((tid & 31) == 0) sdet[tid >> 5] = det;
    __syncthreads();
    int is64 = ((sdet[0] | sdet[1] | sdet[2] | sdet[3]) == 0) ? 1 : 0;

    const float* sc = g_score + b * T_;
    int base = b * T_;

    float mx = -3.402823466e38f;
    for (int t = tid; t < T_; t += 128) {
        int gid = (int)(is64 ? raw[2 * (base + t)] : raw[base + t]);
        if (gid == g) mx = fmaxf(mx, sc[t]);
    }
    #pragma unroll
    for (int o = 16; o; o >>= 1) mx = fmaxf(mx, __shfl_xor_sync(0xffffffffu, mx, o));
    __shared__ float sm[4];
    if ((tid & 31) == 0) sm[tid >> 5] = mx;
    __syncthreads();
    mx = fmaxf(fmaxf(sm[0], sm[1]), fmaxf(sm[2], sm[3]));
    if (mx < -1e37f) mx = 0.f;   // empty group guard

    float sum = 0.f;
    for (int t = tid; t < T_; t += 128) {
        int gid = (int)(is64 ? raw[2 * (base + t)] : raw[base + t]);
        if (gid == g) sum += __expf(sc[t] - mx);
    }
    #pragma unroll
    for (int o = 16; o; o >>= 1) sum += __shfl_xor_sync(0xffffffffu, sum, o);
    __shared__ float ssum[4];
    if ((tid & 31) == 0) ssum[tid >> 5] = sum;
    __syncthreads();
    float S = ssum[0] + ssum[1] + ssum[2] + ssum[3];
    float rden = (S > 0.f) ? (1.0f / S) : 0.f;

    float gb = __int_as_float(g);
    for (int t = tid; t < T_; t += 128) {
        int gid = (int)(is64 ? raw[2 * (base + t)] : raw[base + t]);
        if (gid == g) {
            float c = __expf(sc[t] - mx) * rden * g_invrms[base + t];
            g_wg[base + t] = make_float2(c, gb);
        }
    }
}

// ---------------------------------------------------------------------------
// Kernel 3: group pooling v5.
// - x loaded DIRECTLY via volatile LDG (no smem staging): halves smem traffic.
//   16 loads/warp/tile, front-batched by construction, + 2-tile register
//   double buffer (xa/xb) so tile i+1 loads overlap tile i compute.
// - coef ring: S=4 cp.async stages of 512B.
// - acc: 4 warps x 2 parity x 8KB = 64KB, provably-disjoint parity (&2047).
// - smem ~66KB -> 3 CTAs/SM -> 12 warps x 2KB = 24KB in flight per SM.
// Grid (32 col-chunks, 8 batches, 4 token-splits) = 1024 CTAs x 16 tiles.
// ---------------------------------------------------------------------------
#define POOL_S      4
#define POOL_ACC_F  (4 * 2 * 2048)           // 16384 floats
#define POOL_SWG_F  (POOL_S * 64 * 2)        // 512 floats
#define POOL_SMEM_B ((POOL_ACC_F + POOL_SWG_F) * 4)

__global__ void __launch_bounds__(128) pool_kernel(
    const float* __restrict__ x, const float* __restrict__ norm_w) {
    extern __shared__ float smem[];
    float* acc = smem;                        // 16384 floats
    float* swg = smem + POOL_ACC_F;           // 4 x 128 floats

    int tid  = threadIdx.x;
    int lane = tid & 31;
    int w    = tid >> 5;
    int ch   = blockIdx.x;           // 0..31 (column chunk of 32)
    int b    = blockIdx.y;           // 0..7
    int z    = blockIdx.z;           // 0..3 (token split: 16 tiles of 64 tokens)

    for (int i = tid; i < POOL_ACC_F; i += 128) acc[i] = 0.f;

    const float*  xb0 = x + (size_t)b * T_ * D_ + (size_t)ch * 32 + lane;
    const float2* wgb = g_wg + b * T_;
    int tbase = z * 1024;            // first token of this split

    uint32_t swg_base = (uint32_t)__cvta_generic_to_shared(swg);

    // coef stage issue (warp 0 only inside; called by all threads)
    auto issue = [&](int tile, int s) {
        if (tid < 32) {
            int t0 = tbase + tile * 64;
            uint32_t d2 = swg_base + (uint32_t)(s * 128) * 4u + (uint32_t)tid * 16u;
            cp16(d2, (const char*)(wgb + t0) + tid * 16);
        }
    };
    // load one tile's x for this warp into regs (volatile => stays batched)
    int lt0 = w * 16;
    auto xload = [&](int tile, float* xs) {
        const float* p = xb0 + (size_t)(tbase + tile * 64 + lt0) * D_;
        #pragma unroll
        for (int k = 0; k < 16; k++) xs[k] = vldg(p + (size_t)k * D_);
    };
    auto compute = [&](int s, const float* xs) {
        float* aw = acc + w * 4096;
        const float2* swgb = (const float2*)(swg + s * 128);
        #pragma unroll
        for (int kb = 0; kb < 8; kb++) {
            float2 w0 = swgb[lt0 + 2 * kb];
            float2 w1 = swgb[lt0 + 2 * kb + 1];
            // &2047 is a no-op (g<64) but PROVES the regions disjoint,
            // letting the two RMW chains overlap.
            int i0 = ((__float_as_int(w0.y) * 32 + lane) & 2047);
            int i1 = ((__float_as_int(w1.y) * 32 + lane) & 2047) + 2048;
            float v0 = aw[i0];
            float v1 = aw[i1];
            aw[i0] = fmaf(w0.x, xs[2 * kb], v0);
            aw[i1] = fmaf(w1.x, xs[2 * kb + 1], v1);
        }
    };

    issue(0, 0); cp_commit();
    issue(1, 1); cp_commit();
    issue(2, 2); cp_commit();

    float xa[16], xb[16];
    xload(0, xa);                     // tile 0 x in flight

    #pragma unroll 1
    for (int i = 0; i < 16; i += 2) {
        // tile i (even) — uses xa
        cp_wait<2>();
        __syncthreads();              // coef tile i visible; acc zeroed (i==0)
        issue(i + 3, (i + 3) & 3);    // tiles 17,18 never consumed: harmless
        cp_commit();
        xload(i + 1, xb);             // overlap next tile's loads with compute
        compute(i & 3, xa);
        // tile i+1 (odd) — uses xb
        cp_wait<2>();
        __syncthreads();
        issue(i + 4, (i + 4) & 3);
        cp_commit();
        if (i + 2 < 16) xload(i + 2, xa);
        compute((i + 1) & 3, xb);
    }
    __syncthreads();                  // all compute done before cross-warp flush

    // Flush: sum 8 copies per (g, col), apply norm_w, write partial p.
    float* pout = g_p4[z] + (size_t)b * G_ * D_ + (size_t)ch * 32;
    for (int i = tid; i < G_ * 32; i += 128) {
        int g = i >> 5, c = i & 31;
        float s = 0.f;
        #pragma unroll
        for (int ww = 0; ww < 4; ww++)
            #pragma unroll
            for (int q = 0; q < 2; q++)
                s += acc[ww * 4096 + q * 2048 + g * 32 + c];
        pout[(size_t)g * D_ + c] = s * norm_w[ch * 32 + c];
    }
}

// ---------------------------------------------------------------------------
// Kernel 4: out = p @ Wv^T, split-K=4.  M=512, N=1024, K=1024.
// A is read as sum of 4 z-split partials (folded into the load).
// ---------------------------------------------------------------------------
__global__ void __launch_bounds__(256) gemm_kernel(const float* __restrict__ Wv) {
    __shared__ float As[8][128];
    __shared__ float Bs[8][128];
    int tid = threadIdx.x;
    int bn = blockIdx.x, bm = blockIdx.y, ks = blockIdx.z;
    int row = tid >> 1;            // 0..127 (loader row)
    int kq  = (tid & 1) * 4;       // loader k quad
    int tx = tid & 15, ty = tid >> 4;

    size_t aoff = (size_t)(bm * 128 + row) * D_ + ks * 256 + kq;
    const float* Bg = Wv + (size_t)(bn * 128 + row) * D_ + ks * 256 + kq;

    u64 acc2[8][4];
    #pragma unroll
    for (int r = 0; r < 8; r++)
        #pragma unroll
        for (int c = 0; c < 4; c++) acc2[r][c] = 0ull;

    for (int k0 = 0; k0 < 256; k0 += 8) {
        float4 a0v = *(const float4*)(g_p4[0] + aoff + k0);
        float4 a1v = *(const float4*)(g_p4[1] + aoff + k0);
        float4 a2v = *(const float4*)(g_p4[2] + aoff + k0);
        float4 a3v = *(const float4*)(g_p4[3] + aoff + k0);
        float4 bv  = *(const float4*)(Bg + k0);
        float4 av  = make_float4((a0v.x + a1v.x) + (a2v.x + a3v.x),
                                 (a0v.y + a1v.y) + (a2v.y + a3v.y),
                                 (a0v.z + a1v.z) + (a2v.z + a3v.z),
                                 (a0v.w + a1v.w) + (a2v.w + a3v.w));
        __syncthreads();
        As[kq + 0][row] = av.x; As[kq + 1][row] = av.y;
        As[kq + 2][row] = av.z; As[kq + 3][row] = av.w;
        Bs[kq + 0][row] = bv.x; Bs[kq + 1][row] = bv.y;
        Bs[kq + 2][row] = bv.z; Bs[kq + 3][row] = bv.w;
        __syncthreads();
        #pragma unroll
        for (int kk = 0; kk < 8; kk++) {
            float4 a0 = *(const float4*)&As[kk][ty * 8];
            float4 a1 = *(const float4*)&As[kk][ty * 8 + 4];
            ulonglong2 bb0 = *(const ulonglong2*)&Bs[kk][tx * 8];
            ulonglong2 bb1 = *(const ulonglong2*)&Bs[kk][tx * 8 + 4];
            u64 bc[4] = {bb0.x, bb0.y, bb1.x, bb1.y};
            float a[8] = {a0.x, a0.y, a0.z, a0.w, a1.x, a1.y, a1.z, a1.w};
            #pragma unroll
            for (int r = 0; r < 8; r++) {
                u64 ar = pack2(a[r]);
                #pragma unroll
                for (int c = 0; c < 4; c++)
                    acc2[r][c] = fma2(ar, bc[c], acc2[r][c]);
            }
        }
    }

    float* op = g_out_part[ks] + (size_t)(bm * 128 + ty * 8) * D_ + bn * 128 + tx * 8;
    #pragma unroll
    for (int r = 0; r < 8; r++) {
        *(ulonglong2*)(op + (size_t)r * D_)     = make_ulonglong2(acc2[r][0], acc2[r][1]);
        *(ulonglong2*)(op + (size_t)r * D_ + 4) = make_ulonglong2(acc2[r][2], acc2[r][3]);
    }
}

// Kernel 5: fixed-order split-K reduction into d_out
__global__ void gemm_reduce_kernel(float* __restrict__ out) {
    int idx = blockIdx.x * 256 + threadIdx.x;
    if (idx < BG_ * D_) {
        float s = g_out_part[0][idx] + g_out_part[1][idx]
                + g_out_part[2][idx] + g_out_part[3][idx];
        out[idx] = s;
    }
}

// ---------------------------------------------------------------------------
// Launch — 6 launches; pool at index 3 (ncu's sampled launch)
// ---------------------------------------------------------------------------
extern "C" void kernel_launch(void* const* d_in, const int* in_sizes, int n_in,
                              void* d_out, int out_size) {
    const float* x = nullptr;
    const void*  gid = nullptr;
    const float* query = nullptr;
    const float* norm_w = nullptr;
    const float* Wk = nullptr;
    const float* Wv = nullptr;

    for (int i = 0; i < n_in; i++) {
        int s = in_sizes[i];
        if (s == B_ * T_ * D_)      x = (const float*)d_in[i];
        else if (s == BT_)          gid = d_in[i];
        else if (s == D_) {
            if (!query) query = (const float*)d_in[i];
            else        norm_w = (const float*)d_in[i];
        } else if (s == D_ * D_) {
            if (!Wk) Wk = (const float*)d_in[i];
            else     Wv = (const float*)d_in[i];
        }
    }
    if (!x || !gid || !query || !norm_w || !Wk || !Wv) return;

    float* out = (float*)d_out;
    (void)out_size;

    cudaFuncSetAttribute(pool_kernel,
                         cudaFuncAttributeMaxDynamicSharedMemorySize, POOL_SMEM_B);

    qk_kernel<<<64, 256>>>(query, Wk, norm_w);                   // 0
    token_stats_kernel<<<BT_ / 16, 256>>>(x);                    // 1
    seg_softmax_kernel<<<BG_, 128>>>((const unsigned int*)gid);  // 2
    pool_kernel<<<dim3(32, 8, 4), 128, POOL_SMEM_B>>>(x, norm_w);// 3  <- profiled
    gemm_kernel<<<dim3(8, 4, 4), 256>>>(Wv);                     // 4
    gemm_reduce_kernel<<<(BG_ * D_ + 255) / 256, 256>>>(out);    // 5
}

// round 12
// speedup vs baseline: 1.2160x; 1.2160x over previous
#include <cuda_runtime.h>
#include <cstdint>
#include <cstddef>

// Problem constants (AttentionPool: B=8, T=4096, D=1024, G=64)
#define B_  8
#define T_  4096
#define D_  1024
#define G_  64
#define BT_ (B_ * T_)           // 32768 tokens
#define BG_ (B_ * G_)           // 512 (b,g) pairs
#define EPS_ 1.1920928955078125e-07f   // finfo(float32).eps
#define INV_SQRT_D_ (1.0f / 32.0f)

typedef unsigned long long u64;

// ---------------------------------------------------------------------------
// Device scratch (static — no allocations allowed)
// ---------------------------------------------------------------------------
__device__ float  g_qkd[D_];                // norm_w * (Wk^T q)
__device__ float  g_score[BT_];             // per-token score
__device__ float  g_invrms[BT_];            // per-token 1/rms
__device__ float2 g_wg[BT_];                // {coef, group_as_bits} per token
__device__ float  g_p4[4][BG_ * D_];        // pooled h partials (token split 4)
__device__ float  g_out_part[4][BG_ * D_];  // split-K GEMM partials

// ---------------------------------------------------------------------------
// helpers
// ---------------------------------------------------------------------------
__device__ __forceinline__ u64 pack2(float v) {
    u64 r; asm("mov.b64 %0, {%1, %1};" : "=l"(r) : "f"(v)); return r;
}
__device__ __forceinline__ u64 fma2(u64 a, u64 b, u64 c) {
    u64 d; asm("fma.rn.f32x2 %0, %1, %2, %3;" : "=l"(d) : "l"(a), "l"(b), "l"(c));
    return d;
}
__device__ __forceinline__ void cp16(uint32_t smem_dst, const void* gsrc) {
    asm volatile("cp.async.cg.shared.global [%0], [%1], 16;"
                 :: "r"(smem_dst), "l"(gsrc));
}
__device__ __forceinline__ void cp_commit() {
    asm volatile("cp.async.commit_group;");
}
template <int N>
__device__ __forceinline__ void cp_wait() {
    asm volatile("cp.async.wait_group %0;" :: "n"(N));
}
__device__ __forceinline__ float4 vldg4(const float* p) {
    float4 r;
    asm volatile("ld.global.nc.v4.f32 {%0,%1,%2,%3}, [%4];"
                 : "=f"(r.x), "=f"(r.y), "=f"(r.z), "=f"(r.w) : "l"(p));
    return r;
}

// ---------------------------------------------------------------------------
// Kernel 0: fused qk GEMV  qkd[d] = norm_w[d] * sum_e query[e] * Wk[e,d]
// ---------------------------------------------------------------------------
__global__ void __launch_bounds__(256) qk_kernel(
    const float* __restrict__ query, const float* __restrict__ Wk,
    const float* __restrict__ norm_w) {
    int di = threadIdx.x & 15;
    int eg = threadIdx.x >> 4;
    int d  = blockIdx.x * 16 + di;
    float s = 0.f;
    #pragma unroll 8
    for (int e = eg; e < D_; e += 16) s += query[e] * Wk[(size_t)e * D_ + d];
    __shared__ float red[16][17];
    red[eg][di] = s;
    __syncthreads();
    if (threadIdx.x < 16) {
        int dd = blockIdx.x * 16 + threadIdx.x;
        float t = 0.f;
        #pragma unroll
        for (int i = 0; i < 16; i++) t += red[i][threadIdx.x];
        g_qkd[dd] = t * norm_w[dd];
    }
}

// ---------------------------------------------------------------------------
// Kernel 1: per-token stats v3 (R9, measured ~5us better than v2):
// 2 tokens/warp, 16 volatile LDG.128 front-batched by construction.
// ---------------------------------------------------------------------------
__global__ void __launch_bounds__(256) token_stats_kernel(const float* __restrict__ x) {
    int w    = threadIdx.x >> 5;
    int lane = threadIdx.x & 31;
    int tok0 = blockIdx.x * 16 + w * 2;
    int tok1 = tok0 + 1;
    const float* xt0 = x + (size_t)tok0 * D_;
    const float* xt1 = x + (size_t)tok1 * D_;
    const float4* qk = (const float4*)g_qkd;

    float4 a[8], c[8];
    #pragma unroll
    for (int r = 0; r < 8; r++) a[r] = vldg4(xt0 + (r * 32 + lane) * 4);
    #pragma unroll
    for (int r = 0; r < 8; r++) c[r] = vldg4(xt1 + (r * 32 + lane) * 4);

    float ss0 = 0.f, dq0 = 0.f, ss1 = 0.f, dq1 = 0.f;
    #pragma unroll
    for (int r = 0; r < 8; r++) {
        float4 q = qk[r * 32 + lane];
        float4 v = a[r];
        ss0 += v.x * v.x + v.y * v.y + v.z * v.z + v.w * v.w;
        dq0 += v.x * q.x + v.y * q.y + v.z * q.z + v.w * q.w;
        float4 u = c[r];
        ss1 += u.x * u.x + u.y * u.y + u.z * u.z + u.w * u.w;
        dq1 += u.x * q.x + u.y * q.y + u.z * q.z + u.w * q.w;
    }
    #pragma unroll
    for (int o = 16; o; o >>= 1) {
        ss0 += __shfl_xor_sync(0xffffffffu, ss0, o);
        dq0 += __shfl_xor_sync(0xffffffffu, dq0, o);
        ss1 += __shfl_xor_sync(0xffffffffu, ss1, o);
        dq1 += __shfl_xor_sync(0xffffffffu, dq1, o);
    }
    if (lane == 0) {
        float ir0 = rsqrtf(ss0 * (1.0f / (float)D_) + EPS_);
        g_invrms[tok0] = ir0;
        g_score[tok0]  = dq0 * ir0 * INV_SQRT_D_;
        float ir1 = rsqrtf(ss1 * (1.0f / (float)D_) + EPS_);
        g_invrms[tok1] = ir1;
        g_score[tok1]  = dq1 * ir1 * INV_SQRT_D_;
    }
}

// ---------------------------------------------------------------------------
// Kernel 2: segment softmax per (b,g) + per-token coef write.
// ---------------------------------------------------------------------------
__global__ void __launch_bounds__(128) seg_softmax_kernel(const unsigned int* __restrict__ raw) {
    int b = blockIdx.x >> 6;
    int g = blockIdx.x & 63;
    int tid = threadIdx.x;

    unsigned int det = raw[2 * tid + 1];
    #pragma unroll
    for (int o = 16; o; o >>= 1) det |= __shfl_xor_sync(0xffffffffu, det, o);
    __shared__ unsigned int sdet[4];
    if ((tid & 31) == 0) sdet[tid >> 5] = det;
    __syncthreads();
    int is64 = ((sdet[0] | sdet[1] | sdet[2] | sdet[3]) == 0) ? 1 : 0;

    const float* sc = g_score + b * T_;
    int base = b * T_;

    float mx = -3.402823466e38f;
    for (int t = tid; t < T_; t += 128) {
        int gid = (int)(is64 ? raw[2 * (base + t)] : raw[base + t]);
        if (gid == g) mx = fmaxf(mx, sc[t]);
    }
    #pragma unroll
    for (int o = 16; o; o >>= 1) mx = fmaxf(mx, __shfl_xor_sync(0xffffffffu, mx, o));
    __shared__ float sm[4];
    if ((tid & 31) == 0) sm[tid >> 5] = mx;
    __syncthreads();
    mx = fmaxf(fmaxf(sm[0], sm[1]), fmaxf(sm[2], sm[3]));
    if (mx < -1e37f) mx = 0.f;   // empty group guard

    float sum = 0.f;
    for (int t = tid; t < T_; t += 128) {
        int gid = (int)(is64 ? raw[2 * (base + t)] : raw[base + t]);
        if (gid == g) sum += __expf(sc[t] - mx);
    }
    #pragma unroll
    for (int o = 16; o; o >>= 1) sum += __shfl_xor_sync(0xffffffffu, sum, o);
    __shared__ float ssum[4];
    if ((tid & 31) == 0) ssum[tid >> 5] = sum;
    __syncthreads();
    float S = ssum[0] + ssum[1] + ssum[2] + ssum[3];
    float rden = (S > 0.f) ? (1.0f / S) : 0.f;

    float gb = __int_as_float(g);
    for (int t = tid; t < T_; t += 128) {
        int gid = (int)(is64 ? raw[2 * (base + t)] : raw[base + t]);
        if (gid == g) {
            float c = __expf(sc[t] - mx) * rden * g_invrms[base + t];
            g_wg[base + t] = make_float2(c, gb);
        }
    }
}

// ---------------------------------------------------------------------------
// Kernel 3: group pooling v4 — VERBATIM from R8 (measured 44.4us, DRAM 38%).
// S=4 cp.async ring, one barrier per tile, issue-before-compute.
// Provably-disjoint parity regions (&2047). z-split 4 => 1024 CTAs x 16 tiles.
// smem: acc 64KB + 4x(8KB x + 0.5KB wg) = ~98KB -> 2 CTAs/SM.
// ---------------------------------------------------------------------------
#define POOL_S      4
#define POOL_ACC_F  (4 * 2 * 2048)           // 16384 floats
#define POOL_SX_F   (POOL_S * 64 * 32)       // 8192 floats
#define POOL_SWG_F  (POOL_S * 64 * 2)        // 512 floats
#define POOL_SMEM_B ((POOL_ACC_F + POOL_SX_F + POOL_SWG_F) * 4)

__global__ void __launch_bounds__(128) pool_kernel(
    const float* __restrict__ x, const float* __restrict__ norm_w) {
    extern __shared__ float smem[];
    float* acc = smem;                        // 16384 floats
    float* sx  = smem + POOL_ACC_F;           // 4 x 2048 floats
    float* swg = sx + POOL_SX_F;              // 4 x 128 floats

    int tid  = threadIdx.x;
    int lane = tid & 31;
    int w    = tid >> 5;
    int ch   = blockIdx.x;           // 0..31 (column chunk of 32)
    int b    = blockIdx.y;           // 0..7
    int z    = blockIdx.z;           // 0..3 (token split: 16 tiles of 64 tokens)

    for (int i = tid; i < POOL_ACC_F; i += 128) acc[i] = 0.f;

    const float*  xb  = x + (size_t)b * T_ * D_ + (size_t)ch * 32;
    const float2* wgb = g_wg + b * T_;
    int tbase = z * 1024;            // first token of this split

    uint32_t sx_base  = (uint32_t)__cvta_generic_to_shared(sx);
    uint32_t swg_base = (uint32_t)__cvta_generic_to_shared(swg);

    // issue one tile's loads into stage buffer s
    auto issue = [&](int tile, int s) {
        int t0 = tbase + tile * 64;
        int rrow = tid >> 3;          // 0..15
        int rcol = (tid & 7) * 4;     // 0,4,..28
        uint32_t dst = sx_base + (uint32_t)(s * 2048 + rrow * 32 + rcol) * 4u;
        const float* src = xb + (size_t)(t0 + rrow) * D_ + rcol;
        #pragma unroll
        for (int p = 0; p < 4; p++)
            cp16(dst + p * 16u * 32u * 4u, src + (size_t)p * 16 * D_);
        if (tid < 32) {
            uint32_t d2 = swg_base + (uint32_t)(s * 128) * 4u + (uint32_t)tid * 16u;
            cp16(d2, (const char*)(wgb + t0) + tid * 16);
        }
    };

    issue(0, 0); cp_commit();
    issue(1, 1); cp_commit();
    issue(2, 2); cp_commit();

    float* aw = acc + w * 4096;
    for (int i = 0; i < 16; i++) {
        cp_wait<2>();                 // tile i resident
        __syncthreads();              // visible to all; slot free; acc zeroed (i==0)
        if (i + 3 < 16) issue(i + 3, (i + 3) & 3);
        cp_commit();                  // one group per iteration (maybe empty)
        int s = i & 3;
        const float*  sxb  = sx + s * 2048;
        const float2* swgb = (const float2*)(swg + s * 128);
        int lt0 = w * 16;
        #pragma unroll
        for (int kb = 0; kb < 8; kb++) {
            float2 w0 = swgb[lt0 + 2 * kb];
            float2 w1 = swgb[lt0 + 2 * kb + 1];
            float  x0 = sxb[(lt0 + 2 * kb) * 32 + lane];
            float  x1 = sxb[(lt0 + 2 * kb + 1) * 32 + lane];
            // &2047 is a no-op (g<64) but PROVES the two regions disjoint,
            // so the compiler can overlap the two RMW chains.
            int i0 = ((__float_as_int(w0.y) * 32 + lane) & 2047);
            int i1 = ((__float_as_int(w1.y) * 32 + lane) & 2047) + 2048;
            float v0 = aw[i0];
            float v1 = aw[i1];
            aw[i0] = fmaf(w0.x, x0, v0);
            aw[i1] = fmaf(w1.x, x1, v1);
        }
    }
    __syncthreads();                  // all compute done before cross-warp flush

    // Flush: sum 8 copies per (g, col), apply norm_w, write partial p.
    float* pout = g_p4[z] + (size_t)b * G_ * D_ + (size_t)ch * 32;
    for (int i = tid; i < G_ * 32; i += 128) {
        int g = i >> 5, c = i & 31;
        float s = 0.f;
        #pragma unroll
        for (int ww = 0; ww < 4; ww++)
            #pragma unroll
            for (int q = 0; q < 2; q++)
                s += acc[ww * 4096 + q * 2048 + g * 32 + c];
        pout[(size_t)g * D_ + c] = s * norm_w[ch * 32 + c];
    }
}

// ---------------------------------------------------------------------------
// Kernel 4: out = p @ Wv^T, split-K=4.  M=512, N=1024, K=1024.
// A is read as sum of 4 z-split partials (folded into the load).
// ---------------------------------------------------------------------------
__global__ void __launch_bounds__(256) gemm_kernel(const float* __restrict__ Wv) {
    __shared__ float As[8][128];
    __shared__ float Bs[8][128];
    int tid = threadIdx.x;
    int bn = blockIdx.x, bm = blockIdx.y, ks = blockIdx.z;
    int row = tid >> 1;            // 0..127 (loader row)
    int kq  = (tid & 1) * 4;       // loader k quad
    int tx = tid & 15, ty = tid >> 4;

    size_t aoff = (size_t)(bm * 128 + row) * D_ + ks * 256 + kq;
    const float* Bg = Wv + (size_t)(bn * 128 + row) * D_ + ks * 256 + kq;

    u64 acc2[8][4];
    #pragma unroll
    for (int r = 0; r < 8; r++)
        #pragma unroll
        for (int c = 0; c < 4; c++) acc2[r][c] = 0ull;

    for (int k0 = 0; k0 < 256; k0 += 8) {
        float4 a0v = *(const float4*)(g_p4[0] + aoff + k0);
        float4 a1v = *(const float4*)(g_p4[1] + aoff + k0);
        float4 a2v = *(const float4*)(g_p4[2] + aoff + k0);
        float4 a3v = *(const float4*)(g_p4[3] + aoff + k0);
        float4 bv  = *(const float4*)(Bg + k0);
        float4 av  = make_float4((a0v.x + a1v.x) + (a2v.x + a3v.x),
                                 (a0v.y + a1v.y) + (a2v.y + a3v.y),
                                 (a0v.z + a1v.z) + (a2v.z + a3v.z),
                                 (a0v.w + a1v.w) + (a2v.w + a3v.w));
        __syncthreads();
        As[kq + 0][row] = av.x; As[kq + 1][row] = av.y;
        As[kq + 2][row] = av.z; As[kq + 3][row] = av.w;
        Bs[kq + 0][row] = bv.x; Bs[kq + 1][row] = bv.y;
        Bs[kq + 2][row] = bv.z; Bs[kq + 3][row] = bv.w;
        __syncthreads();
        #pragma unroll
        for (int kk = 0; kk < 8; kk++) {
            float4 a0 = *(const float4*)&As[kk][ty * 8];
            float4 a1 = *(const float4*)&As[kk][ty * 8 + 4];
            ulonglong2 bb0 = *(const ulonglong2*)&Bs[kk][tx * 8];
            ulonglong2 bb1 = *(const ulonglong2*)&Bs[kk][tx * 8 + 4];
            u64 bc[4] = {bb0.x, bb0.y, bb1.x, bb1.y};
            float a[8] = {a0.x, a0.y, a0.z, a0.w, a1.x, a1.y, a1.z, a1.w};
            #pragma unroll
            for (int r = 0; r < 8; r++) {
                u64 ar = pack2(a[r]);
                #pragma unroll
                for (int c = 0; c < 4; c++)
                    acc2[r][c] = fma2(ar, bc[c], acc2[r][c]);
            }
        }
    }

    float* op = g_out_part[ks] + (size_t)(bm * 128 + ty * 8) * D_ + bn * 128 + tx * 8;
    #pragma unroll
    for (int r = 0; r < 8; r++) {
        *(ulonglong2*)(op + (size_t)r * D_)     = make_ulonglong2(acc2[r][0], acc2[r][1]);
        *(ulonglong2*)(op + (size_t)r * D_ + 4) = make_ulonglong2(acc2[r][2], acc2[r][3]);
    }
}

// Kernel 5: fixed-order split-K reduction into d_out
__global__ void gemm_reduce_kernel(float* __restrict__ out) {
    int idx = blockIdx.x * 256 + threadIdx.x;
    if (idx < BG_ * D_) {
        float s = g_out_part[0][idx] + g_out_part[1][idx]
                + g_out_part[2][idx] + g_out_part[3][idx];
        out[idx] = s;
    }
}

// ---------------------------------------------------------------------------
// Launch — 6 launches; pool at index 3 (ncu's sampled launch)
// ---------------------------------------------------------------------------
extern "C" void kernel_launch(void* const* d_in, const int* in_sizes, int n_in,
                              void* d_out, int out_size) {
    const float* x = nullptr;
    const void*  gid = nullptr;
    const float* query = nullptr;
    const float* norm_w = nullptr;
    const float* Wk = nullptr;
    const float* Wv = nullptr;

    for (int i = 0; i < n_in; i++) {
        int s = in_sizes[i];
        if (s == B_ * T_ * D_)      x = (const float*)d_in[i];
        else if (s == BT_)          gid = d_in[i];
        else if (s == D_) {
            if (!query) query = (const float*)d_in[i];
            else        norm_w = (const float*)d_in[i];
        } else if (s == D_ * D_) {
            if (!Wk) Wk = (const float*)d_in[i];
            else     Wv = (const float*)d_in[i];
        }
    }
    if (!x || !gid || !query || !norm_w || !Wk || !Wv) return;

    float* out = (float*)d_out;
    (void)out_size;

    cudaFuncSetAttribute(pool_kernel,
                         cudaFuncAttributeMaxDynamicSharedMemorySize, POOL_SMEM_B);

    qk_kernel<<<64, 256>>>(query, Wk, norm_w);                   // 0
    token_stats_kernel<<<BT_ / 16, 256>>>(x);                    // 1
    seg_softmax_kernel<<<BG_, 128>>>((const unsigned int*)gid);  // 2
    pool_kernel<<<dim3(32, 8, 4), 128, POOL_SMEM_B>>>(x, norm_w);// 3  <- profiled
    gemm_kernel<<<dim3(8, 4, 4), 256>>>(Wv);                     // 4
    gemm_reduce_kernel<<<(BG_ * D_ + 255) / 256, 256>>>(out);    // 5
}

// round 14
// speedup vs baseline: 1.3590x; 1.1176x over previous
#include <cuda_runtime.h>
#include <cstdint>
#include <cstddef>

// Problem constants (AttentionPool: B=8, T=4096, D=1024, G=64)
#define B_  8
#define T_  4096
#define D_  1024
#define G_  64
#define BT_ (B_ * T_)           // 32768 tokens
#define BG_ (B_ * G_)           // 512 (b,g) pairs
#define EPS_ 1.1920928955078125e-07f   // finfo(float32).eps
#define INV_SQRT_D_ (1.0f / 32.0f)

typedef unsigned long long u64;

// ---------------------------------------------------------------------------
// Device scratch (static — no allocations allowed)
// ---------------------------------------------------------------------------
__device__ float  g_qkd[D_];                // norm_w * (Wk^T q)
__device__ float  g_score[BT_];             // per-token score
__device__ float  g_invrms[BT_];            // per-token 1/rms
__device__ float2 g_list[BG_ * T_];         // per-(b,g) ordered {coef, idx}
__device__ int    g_cnt[BG_];               // per-(b,g) token count
__device__ float  g_p[BG_ * D_];            // pooled h (incl norm_w)
__device__ float  g_out_part[4][BG_ * D_];  // split-K GEMM partials

// ---------------------------------------------------------------------------
// helpers
// ---------------------------------------------------------------------------
__device__ __forceinline__ u64 pack2(float v) {
    u64 r; asm("mov.b64 %0, {%1, %1};" : "=l"(r) : "f"(v)); return r;
}
__device__ __forceinline__ u64 fma2(u64 a, u64 b, u64 c) {
    u64 d; asm("fma.rn.f32x2 %0, %1, %2, %3;" : "=l"(d) : "l"(a), "l"(b), "l"(c));
    return d;
}
__device__ __forceinline__ float4 vldg4(const float* p) {
    float4 r;
    asm volatile("ld.global.nc.v4.f32 {%0,%1,%2,%3}, [%4];"
                 : "=f"(r.x), "=f"(r.y), "=f"(r.z), "=f"(r.w) : "l"(p));
    return r;
}

// ---------------------------------------------------------------------------
// Kernel 0: fused qk GEMV  qkd[d] = norm_w[d] * sum_e query[e] * Wk[e,d]
// ---------------------------------------------------------------------------
__global__ void __launch_bounds__(256) qk_kernel(
    const float* __restrict__ query, const float* __restrict__ Wk,
    const float* __restrict__ norm_w) {
    int di = threadIdx.x & 15;
    int eg = threadIdx.x >> 4;
    int d  = blockIdx.x * 16 + di;
    float s = 0.f;
    #pragma unroll 8
    for (int e = eg; e < D_; e += 16) s += query[e] * Wk[(size_t)e * D_ + d];
    __shared__ float red[16][17];
    red[eg][di] = s;
    __syncthreads();
    if (threadIdx.x < 16) {
        int dd = blockIdx.x * 16 + threadIdx.x;
        float t = 0.f;
        #pragma unroll
        for (int i = 0; i < 16; i++) t += red[i][threadIdx.x];
        g_qkd[dd] = t * norm_w[dd];
    }
}

// ---------------------------------------------------------------------------
// Kernel 1: per-token stats — 2 tokens/warp, 16 volatile LDG.128.
// ---------------------------------------------------------------------------
__global__ void __launch_bounds__(256) token_stats_kernel(const float* __restrict__ x) {
    int w    = threadIdx.x >> 5;
    int lane = threadIdx.x & 31;
    int tok0 = blockIdx.x * 16 + w * 2;
    int tok1 = tok0 + 1;
    const float* xt0 = x + (size_t)tok0 * D_;
    const float* xt1 = x + (size_t)tok1 * D_;
    const float4* qk = (const float4*)g_qkd;

    float4 a[8], c[8];
    #pragma unroll
    for (int r = 0; r < 8; r++) a[r] = vldg4(xt0 + (r * 32 + lane) * 4);
    #pragma unroll
    for (int r = 0; r < 8; r++) c[r] = vldg4(xt1 + (r * 32 + lane) * 4);

    float ss0 = 0.f, dq0 = 0.f, ss1 = 0.f, dq1 = 0.f;
    #pragma unroll
    for (int r = 0; r < 8; r++) {
        float4 q = qk[r * 32 + lane];
        float4 v = a[r];
        ss0 += v.x * v.x + v.y * v.y + v.z * v.z + v.w * v.w;
        dq0 += v.x * q.x + v.y * q.y + v.z * q.z + v.w * q.w;
        float4 u = c[r];
        ss1 += u.x * u.x + u.y * u.y + u.z * u.z + u.w * u.w;
        dq1 += u.x * q.x + u.y * q.y + u.z * q.z + u.w * q.w;
    }
    #pragma unroll
    for (int o = 16; o; o >>= 1) {
        ss0 += __shfl_xor_sync(0xffffffffu, ss0, o);
        dq0 += __shfl_xor_sync(0xffffffffu, dq0, o);
        ss1 += __shfl_xor_sync(0xffffffffu, ss1, o);
        dq1 += __shfl_xor_sync(0xffffffffu, dq1, o);
    }
    if (lane == 0) {
        float ir0 = rsqrtf(ss0 * (1.0f / (float)D_) + EPS_);
        g_invrms[tok0] = ir0;
        g_score[tok0]  = dq0 * ir0 * INV_SQRT_D_;
        float ir1 = rsqrtf(ss1 * (1.0f / (float)D_) + EPS_);
        g_invrms[tok1] = ir1;
        g_score[tok1]  = dq1 * ir1 * INV_SQRT_D_;
    }
}

// ---------------------------------------------------------------------------
// Kernel 2: segment softmax per (b,g) + ORDERED token-list build.
// Each of 128 threads owns a contiguous 32-token chunk; a block-wide
// exclusive scan of per-thread match counts gives each thread its write
// offset, so the list is ordered by token index — fully deterministic.
// ---------------------------------------------------------------------------
__global__ void __launch_bounds__(128) seg_softmax_kernel(const unsigned int* __restrict__ raw) {
    int bg = blockIdx.x;
    int b = bg >> 6;
    int g = bg & 63;
    int tid  = threadIdx.x;
    int lane = tid & 31;
    int wid  = tid >> 5;

    // dtype detect: OR of raw[2t+1], t<128 (<=1KB, in-bounds either way)
    unsigned int det = raw[2 * tid + 1];
    #pragma unroll
    for (int o = 16; o; o >>= 1) det |= __shfl_xor_sync(0xffffffffu, det, o);
    __shared__ unsigned int sdet[4];
    if (lane == 0) sdet[wid] = det;
    __syncthreads();
    int is64 = ((sdet[0] | sdet[1] | sdet[2] | sdet[3]) == 0) ? 1 : 0;

    const float* sc = g_score + b * T_;
    int base = b * T_;

    // Pass 1: max
    float mx = -3.402823466e38f;
    for (int t = tid; t < T_; t += 128) {
        int gid = (int)(is64 ? raw[2 * (base + t)] : raw[base + t]);
        if (gid == g) mx = fmaxf(mx, sc[t]);
    }
    #pragma unroll
    for (int o = 16; o; o >>= 1) mx = fmaxf(mx, __shfl_xor_sync(0xffffffffu, mx, o));
    __shared__ float sm[4];
    if (lane == 0) sm[wid] = mx;
    __syncthreads();
    mx = fmaxf(fmaxf(sm[0], sm[1]), fmaxf(sm[2], sm[3]));
    if (mx < -1e37f) mx = 0.f;   // empty group guard

    // Pass 2: sum of exp
    float sum = 0.f;
    for (int t = tid; t < T_; t += 128) {
        int gid = (int)(is64 ? raw[2 * (base + t)] : raw[base + t]);
        if (gid == g) sum += __expf(sc[t] - mx);
    }
    #pragma unroll
    for (int o = 16; o; o >>= 1) sum += __shfl_xor_sync(0xffffffffu, sum, o);
    __shared__ float ssum[4];
    if (lane == 0) ssum[wid] = sum;
    __syncthreads();
    float S = ssum[0] + ssum[1] + ssum[2] + ssum[3];
    float rden = (S > 0.f) ? (1.0f / S) : 0.f;

    // Pass 3: count matches in my contiguous chunk [tid*32, tid*32+32)
    int t0 = tid * 32;
    int cnt = 0;
    for (int k = 0; k < 32; k++) {
        int t = t0 + k;
        int gid = (int)(is64 ? raw[2 * (base + t)] : raw[base + t]);
        if (gid == g) cnt++;
    }
    // exclusive scan over 128 threads
    int inc = cnt;
    #pragma unroll
    for (int o = 1; o < 32; o <<= 1) {
        int v = __shfl_up_sync(0xffffffffu, inc, o);
        if (lane >= o) inc += v;
    }
    __shared__ int wtot[4];
    if (lane == 31) wtot[wid] = inc;
    __syncthreads();
    int wbase = 0;
    #pragma unroll
    for (int i = 0; i < 4; i++) if (i < wid) wbase += wtot[i];
    int pos = wbase + inc - cnt;      // this thread's first slot

    // Pass 4: write ordered {coef, idx} entries
    float2* lst = g_list + (size_t)bg * T_;
    for (int k = 0; k < 32; k++) {
        int t = t0 + k;
        int gid = (int)(is64 ? raw[2 * (base + t)] : raw[base + t]);
        if (gid == g) {
            float c = __expf(sc[t] - mx) * rden * g_invrms[base + t];
            lst[pos++] = make_float2(c, (float)t);
        }
    }
    if (tid == 0) g_cnt[bg] = wtot[0] + wtot[1] + wtot[2] + wtot[3];
}

// ---------------------------------------------------------------------------
// Kernel 3: group pooling v7 — GATHER, register accumulators, zero smem.
// One CTA per (b,g); 256 threads x 4 cols (float4). Loop over the group's
// token list, 8-deep unrolled LDG.128 + one-iteration-ahead list prefetch.
// Per x element: 1 LDG + 1 FFMA. x read exactly once, fully coalesced.
// Deterministic: fixed accumulation order (list order = token order).
// ---------------------------------------------------------------------------
__global__ void __launch_bounds__(256) pool_kernel(
    const float* __restrict__ x, const float* __restrict__ norm_w) {
    int bg  = blockIdx.x;
    int b   = bg >> 6;
    int tid = threadIdx.x;
    int n   = g_cnt[bg];

    const float2* lst = g_list + (size_t)bg * T_;
    const float*  xb  = x + (size_t)b * T_ * D_ + tid * 4;

    float4 acc = make_float4(0.f, 0.f, 0.f, 0.f);

    float2 e[8];
    #pragma unroll
    for (int j = 0; j < 8; j++)
        e[j] = (j < n) ? lst[j] : make_float2(0.f, 0.f);

    #pragma unroll 1
    for (int i = 0; i < n; i += 8) {
        // prefetch next iteration's list entries (overlaps x loads below)
        float2 en[8];
        #pragma unroll
        for (int j = 0; j < 8; j++)
            en[j] = (i + 8 + j < n) ? lst[i + 8 + j] : make_float2(0.f, 0.f);
        // 8 independent LDG.128 per thread (coef==0 entries read row 0: safe)
        float4 xv[8];
        #pragma unroll
        for (int j = 0; j < 8; j++)
            xv[j] = vldg4(xb + (size_t)__float2int_rn(e[j].y) * D_);
        #pragma unroll
        for (int j = 0; j < 8; j++) {
            acc.x = fmaf(e[j].x, xv[j].x, acc.x);
            acc.y = fmaf(e[j].x, xv[j].y, acc.y);
            acc.z = fmaf(e[j].x, xv[j].z, acc.z);
            acc.w = fmaf(e[j].x, xv[j].w, acc.w);
        }
        #pragma unroll
        for (int j = 0; j < 8; j++) e[j] = en[j];
    }

    float4 nw = *(const float4*)(norm_w + tid * 4);
    float4 r = make_float4(acc.x * nw.x, acc.y * nw.y, acc.z * nw.z, acc.w * nw.w);
    ((float4*)(g_p + (size_t)bg * D_))[tid] = r;
}

// ---------------------------------------------------------------------------
// Kernel 4: out = p @ Wv^T, split-K=4.  M=512, N=1024, K=1024.
// ---------------------------------------------------------------------------
__global__ void __launch_bounds__(256) gemm_kernel(const float* __restrict__ Wv) {
    __shared__ float As[8][128];
    __shared__ float Bs[8][128];
    int tid = threadIdx.x;
    int bn = blockIdx.x, bm = blockIdx.y, ks = blockIdx.z;
    int row = tid >> 1;            // 0..127 (loader row)
    int kq  = (tid & 1) * 4;       // loader k quad
    int tx = tid & 15, ty = tid >> 4;

    const float* Ag = g_p + (size_t)(bm * 128 + row) * D_ + ks * 256 + kq;
    const float* Bg = Wv  + (size_t)(bn * 128 + row) * D_ + ks * 256 + kq;

    u64 acc2[8][4];
    #pragma unroll
    for (int r = 0; r < 8; r++)
        #pragma unroll
        for (int c = 0; c < 4; c++) acc2[r][c] = 0ull;

    for (int k0 = 0; k0 < 256; k0 += 8) {
        float4 av = *(const float4*)(Ag + k0);
        float4 bv = *(const float4*)(Bg + k0);
        __syncthreads();
        As[kq + 0][row] = av.x; As[kq + 1][row] = av.y;
        As[kq + 2][row] = av.z; As[kq + 3][row] = av.w;
        Bs[kq + 0][row] = bv.x; Bs[kq + 1][row] = bv.y;
        Bs[kq + 2][row] = bv.z; Bs[kq + 3][row] = bv.w;
        __syncthreads();
        #pragma unroll
        for (int kk = 0; kk < 8; kk++) {
            float4 a0 = *(const float4*)&As[kk][ty * 8];
            float4 a1 = *(const float4*)&As[kk][ty * 8 + 4];
            ulonglong2 bb0 = *(const ulonglong2*)&Bs[kk][tx * 8];
            ulonglong2 bb1 = *(const ulonglong2*)&Bs[kk][tx * 8 + 4];
            u64 bc[4] = {bb0.x, bb0.y, bb1.x, bb1.y};
            float a[8] = {a0.x, a0.y, a0.z, a0.w, a1.x, a1.y, a1.z, a1.w};
            #pragma unroll
            for (int r = 0; r < 8; r++) {
                u64 ar = pack2(a[r]);
                #pragma unroll
                for (int c = 0; c < 4; c++)
                    acc2[r][c] = fma2(ar, bc[c], acc2[r][c]);
            }
        }
    }

    float* op = g_out_part[ks] + (size_t)(bm * 128 + ty * 8) * D_ + bn * 128 + tx * 8;
    #pragma unroll
    for (int r = 0; r < 8; r++) {
        *(ulonglong2*)(op + (size_t)r * D_)     = make_ulonglong2(acc2[r][0], acc2[r][1]);
        *(ulonglong2*)(op + (size_t)r * D_ + 4) = make_ulonglong2(acc2[r][2], acc2[r][3]);
    }
}

// Kernel 5: fixed-order split-K reduction into d_out
__global__ void gemm_reduce_kernel(float* __restrict__ out) {
    int idx = blockIdx.x * 256 + threadIdx.x;
    if (idx < BG_ * D_) {
        float s = g_out_part[0][idx] + g_out_part[1][idx]
                + g_out_part[2][idx] + g_out_part[3][idx];
        out[idx] = s;
    }
}

// ---------------------------------------------------------------------------
// Launch — 6 launches; pool at index 3 (ncu's sampled launch)
// ---------------------------------------------------------------------------
extern "C" void kernel_launch(void* const* d_in, const int* in_sizes, int n_in,
                              void* d_out, int out_size) {
    const float* x = nullptr;
    const void*  gid = nullptr;
    const float* query = nullptr;
    const float* norm_w = nullptr;
    const float* Wk = nullptr;
    const float* Wv = nullptr;

    for (int i = 0; i < n_in; i++) {
        int s = in_sizes[i];
        if (s == B_ * T_ * D_)      x = (const float*)d_in[i];
        else if (s == BT_)          gid = d_in[i];
        else if (s == D_) {
            if (!query) query = (const float*)d_in[i];
            else        norm_w = (const float*)d_in[i];
        } else if (s == D_ * D_) {
            if (!Wk) Wk = (const float*)d_in[i];
            else     Wv = (const float*)d_in[i];
        }
    }
    if (!x || !gid || !query || !norm_w || !Wk || !Wv) return;

    float* out = (float*)d_out;
    (void)out_size;

    qk_kernel<<<64, 256>>>(query, Wk, norm_w);                   // 0
    token_stats_kernel<<<BT_ / 16, 256>>>(x);                    // 1
    seg_softmax_kernel<<<BG_, 128>>>((const unsigned int*)gid);  // 2
    pool_kernel<<<BG_, 256>>>(x, norm_w);                        // 3  <- profiled
    gemm_kernel<<<dim3(8, 4, 4), 256>>>(Wv);                     // 4
    gemm_reduce_kernel<<<(BG_ * D_ + 255) / 256, 256>>>(out);    // 5
}